// round 1
// baseline (speedup 1.0000x reference)
#include <cuda_runtime.h>
#include <math.h>

// Problem shape (fixed by the dataset)
#define B_   64
#define S_   256
#define H_   768
#define D_   64
#define NEG_ 4
#define NROW 6            // u, v, 4 negatives per batch
#define EPSF 1e-15f
#define BNDF (1.0f - 1e-7f)

__device__ float g_losses[B_];
__device__ unsigned int g_counter = 0;

// Block-wide sum over 256 threads (8 warps). Deterministic order.
__device__ __forceinline__ float blockReduceSum(float v, volatile float* sbuf) {
    int lane = threadIdx.x & 31;
    int wid  = threadIdx.x >> 5;
#pragma unroll
    for (int o = 16; o > 0; o >>= 1) v += __shfl_down_sync(0xffffffffu, v, o);
    if (lane == 0) sbuf[wid] = v;
    __syncthreads();
    if (wid == 0) {
        float r = (lane < 8) ? sbuf[lane] : 0.f;
#pragma unroll
        for (int o = 4; o > 0; o >>= 1) r += __shfl_down_sync(0xffffffffu, r, o);
        if (lane == 0) sbuf[0] = r;
    }
    __syncthreads();
    float r = sbuf[0];
    __syncthreads();
    return r;
}

__global__ __launch_bounds__(256)
void poincare_kernel(const float* __restrict__ encoded,
                     const float* __restrict__ n_encoded,
                     const float* __restrict__ mask1,
                     const float* __restrict__ mask2,
                     const float* __restrict__ mask_u_neg,
                     const float* __restrict__ W,
                     float* __restrict__ out) {
    __shared__ float xs[NROW][H_];   // gathered token vectors
    __shared__ float ys[NROW][D_];   // mobius_matvec outputs
    __shared__ float sred[8];
    __shared__ int   sidx[NROW];
    __shared__ int   s_last;

    const int b = blockIdx.x;
    const int t = threadIdx.x;

    // ---- 1. one-hot masks -> token indices (S_ == blockDim.x == 256) ----
    {
        if (mask1[b * S_ + t] > 0.5f) sidx[0] = t;
        if (mask2[b * S_ + t] > 0.5f) sidx[1] = t;
#pragma unroll
        for (int j = 0; j < NEG_; j++)
            if (mask_u_neg[(b * NEG_ + j) * S_ + t] > 0.5f) sidx[2 + j] = t;
    }
    __syncthreads();

    // ---- 2. gather the 6 selected rows; accumulate ||x||^2 partials ----
    const float* src[NROW];
    src[0] = encoded + ((size_t)(b * S_ + sidx[0])) * H_;
    src[1] = encoded + ((size_t)(b * S_ + sidx[1])) * H_;
#pragma unroll
    for (int j = 0; j < NEG_; j++)
        src[2 + j] = n_encoded + ((size_t)((b * NEG_ + j) * S_ + sidx[2 + j])) * H_;

    float nsq[NROW];
#pragma unroll
    for (int r = 0; r < NROW; r++) {
        float p = 0.f;
#pragma unroll
        for (int i = t; i < H_; i += 256) {
            float v = src[r][i];
            xs[r][i] = v;
            p += v * v;
        }
        nsq[r] = blockReduceSum(p, sred);   // barrier also publishes xs[r]
    }

    // ---- 3. g = W @ x for all 6 rows, W loaded once ----
    // thread t: output dim d = t/4, quarter q = t%4 (contiguous 192 floats)
    const int d = t >> 2;
    const int q = t & 3;
    const float4* w4 = reinterpret_cast<const float4*>(W + (size_t)d * H_ + q * (H_ / 4));
    float acc[NROW];
#pragma unroll
    for (int r = 0; r < NROW; r++) acc[r] = 0.f;

#pragma unroll 4
    for (int k = 0; k < H_ / 16; k++) {   // 48 float4 per thread
        float4 w = w4[k];
#pragma unroll
        for (int r = 0; r < NROW; r++) {
            float4 xv = reinterpret_cast<const float4*>(&xs[r][q * (H_ / 4)])[k];
            acc[r] = fmaf(w.x, xv.x, acc[r]);
            acc[r] = fmaf(w.y, xv.y, acc[r]);
            acc[r] = fmaf(w.z, xv.z, acc[r]);
            acc[r] = fmaf(w.w, xv.w, acc[r]);
        }
    }
    // reduce the 4 quarter-partials (lanes 4d..4d+3 within a warp)
#pragma unroll
    for (int r = 0; r < NROW; r++) {
        acc[r] += __shfl_xor_sync(0xffffffffu, acc[r], 1);
        acc[r] += __shfl_xor_sync(0xffffffffu, acc[r], 2);
    }

    // ||g||^2 per row (only q==0 lanes contribute, each holds full g[d])
    float gsq[NROW];
#pragma unroll
    for (int r = 0; r < NROW; r++)
        gsq[r] = blockReduceSum((q == 0) ? acc[r] * acc[r] : 0.f, sred);

    // ---- 4. expmap0 + mobius_matvec scalars; write y rows ----
#pragma unroll
    for (int r = 0; r < NROW; r++) {
        float n   = fmaxf(sqrtf(nsq[r]), EPSF);         // clip(||x||, EPS)
        float th  = tanhf(n);
        float sc1 = th / n;                              // expmap0 scale
        float gn  = sqrtf(gsq[r]);
        float mn  = fmaxf(sc1 * gn, EPSF);               // clip(||mx||, EPS)
        float xn  = fmaxf(th, EPSF);                     // clip(||u0||, EPS)
        float at  = atanhf(fminf(xn, BNDF));             // artanh clamp
        float fac = tanhf(mn / xn * at) * sc1 / mn;      // y = fac * g
        if (q == 0) ys[r][d] = fac * acc[r];
    }
    __syncthreads();

    // ---- 5. per-batch scalar losses (threads t<64 hold vector elements) ----
    float ue = (t < D_) ? ys[0][t] : 0.f;
    float ve = (t < D_) ? ys[1][t] : 0.f;

    float nu2 = blockReduceSum(ue * ue, sred);
    float nv2 = blockReduceSum(ve * ve, sred);
    float duv = blockReduceSum(ue * ve, sred);
    float ed  = ue - ve;
    float euclid2 = blockReduceSum(ed * ed, sred);

    // dist(u, v): mobius_add(-u, v); xy = -dot(u,v), x2 = nu2, y2 = nv2
    float A   = 1.f - 2.f * duv + nv2;      // (1 + 2xy + y2)
    float Bc  = 1.f - nu2;                  // (1 - x2)
    float nd  = A * (-ue) + Bc * ve;
    float num2 = blockReduceSum(nd * nd, sred);
    float den  = fmaxf(1.f - 2.f * duv + nu2 * nv2, EPSF);
    float dist_uv = 2.f * atanhf(fminf(sqrtf(num2) / den, BNDF));

    // hyperbolic angle
    float nv = sqrtf(nv2);
    float euclid = sqrtf(euclid2);
    float rad  = fmaxf(1.f + nu2 * nv2 - 2.f * duv, EPSF);
    float denA = fmaxf(nv * euclid * sqrtf(rad), EPSF);
    float cosang = (duv * (1.f + nv2) - nv2 * (1.f + nu2)) / denA;
    float angle = acosf(fminf(fmaxf(cosang, -BNDF), BNDF));

    // negatives
    float Z1 = 0.f;
#pragma unroll
    for (int j = 0; j < NEG_; j++) {
        float we  = (t < D_) ? ys[2 + j][t] : 0.f;
        float nw2 = blockReduceSum(we * we, sred);
        float duw = blockReduceSum(ue * we, sred);
        float A2  = 1.f - 2.f * duw + nw2;
        float nd2 = A2 * (-ue) + (1.f - nu2) * we;
        float m2  = blockReduceSum(nd2 * nd2, sred);
        float dd  = fmaxf(1.f - 2.f * duw + nu2 * nw2, EPSF);
        float dj  = 2.f * atanhf(fminf(sqrtf(m2) / dd, BNDF));
        Z1 += expf(-dj);
    }

    float expneg = expf(-dist_uv);
    float ns_loss = -logf(expneg / (Z1 + expneg));
    // alpha = 0.5: 2*(1-a)*angle + 2*a*ns = angle + ns
    if (t == 0) g_losses[b] = angle + ns_loss;

    // ---- 6. last-block-done: deterministic mean over batches ----
    __threadfence();
    if (t == 0) {
        unsigned int c = atomicAdd(&g_counter, 1u);
        s_last = (c == gridDim.x - 1) ? 1 : 0;
    }
    __syncthreads();
    if (s_last) {
        float v = (t < B_) ? g_losses[t] : 0.f;
        float tot = blockReduceSum(v, sred);
        if (t == 0) {
            out[0] = tot * (1.f / (float)B_);
            g_counter = 0;   // reset for next graph replay
        }
    }
}

extern "C" void kernel_launch(void* const* d_in, const int* in_sizes, int n_in,
                              void* d_out, int out_size) {
    const float* encoded    = (const float*)d_in[0];
    const float* n_encoded  = (const float*)d_in[1];
    const float* mask1      = (const float*)d_in[2];
    const float* mask2      = (const float*)d_in[3];
    const float* mask_u_neg = (const float*)d_in[4];
    const float* W          = (const float*)d_in[5];
    poincare_kernel<<<B_, 256>>>(encoded, n_encoded, mask1, mask2, mask_u_neg, W,
                                 (float*)d_out);
}

// round 2
// speedup vs baseline: 2.2872x; 2.2872x over previous
#include <cuda_runtime.h>
#include <math.h>

#define B_   64
#define S_   256
#define H_   768
#define D_   64
#define NEG_ 4
#define NROW 6
#define EPSF 1e-15f
#define BNDF (1.0f - 1e-7f)

__device__ float g_losses[B_];
__device__ unsigned int g_counter = 0;

__global__ __launch_bounds__(256)
void poincare_kernel(const float* __restrict__ encoded,
                     const float* __restrict__ n_encoded,
                     const float* __restrict__ mask1,
                     const float* __restrict__ mask2,
                     const float* __restrict__ mask_u_neg,
                     const float* __restrict__ W,
                     float* __restrict__ out) {
    __shared__ float xs[NROW][H_];     // gathered token rows
    __shared__ float gt[D_][NROW];     // g = W @ x (pre-factor) per row
    __shared__ float red[NROW][8];     // warp partials of ||x||^2
    __shared__ float gram[11];
    __shared__ int   sidx[NROW];
    __shared__ int   s_last;

    const int b    = blockIdx.x;
    const int t    = threadIdx.x;
    const int lane = t & 31;
    const int w    = t >> 5;

    // Prefetch W chunk j=0 for this warp's 8 output rows (independent of masks)
    const float4* W4 = reinterpret_cast<const float4*>(W);
    float4 wpre[8];
#pragma unroll
    for (int row = 0; row < 8; row++)
        wpre[row] = W4[(8 * w + row) * 192 + lane];

    // ---- Phase 1: one-hot masks -> token indices ----
    if (mask1[b * S_ + t] > 0.5f) sidx[0] = t;
    if (mask2[b * S_ + t] > 0.5f) sidx[1] = t;
#pragma unroll
    for (int j = 0; j < NEG_; j++)
        if (mask_u_neg[(b * NEG_ + j) * S_ + t] > 0.5f) sidx[2 + j] = t;
    __syncthreads();

    // ---- Phase 2: gather 6 rows (18 independent loads), norm^2 partials ----
    const float* src[NROW];
    src[0] = encoded + (size_t)(b * S_ + sidx[0]) * H_;
    src[1] = encoded + (size_t)(b * S_ + sidx[1]) * H_;
#pragma unroll
    for (int j = 0; j < NEG_; j++)
        src[2 + j] = n_encoded + (size_t)((b * NEG_ + j) * S_ + sidx[2 + j]) * H_;

    float v[3][NROW];
#pragma unroll
    for (int c = 0; c < 3; c++) {
        const int i = t + 256 * c;
#pragma unroll
        for (int r = 0; r < NROW; r++) v[c][r] = src[r][i];
    }
    float p[NROW];
#pragma unroll
    for (int r = 0; r < NROW; r++) p[r] = 0.f;
#pragma unroll
    for (int c = 0; c < 3; c++) {
        const int i = t + 256 * c;
#pragma unroll
        for (int r = 0; r < NROW; r++) {
            xs[r][i] = v[c][r];
            p[r] = fmaf(v[c][r], v[c][r], p[r]);
        }
    }
#pragma unroll
    for (int r = 0; r < NROW; r++) {
#pragma unroll
        for (int o = 16; o > 0; o >>= 1)
            p[r] += __shfl_xor_sync(0xffffffffu, p[r], o);
        if (lane == 0) red[r][w] = p[r];
    }
    __syncthreads();   // publishes xs + red

    // ---- Phase 3: matvec, warp w owns output dims 8w..8w+7; coalesced W ----
    float acc[8][NROW];
#pragma unroll
    for (int row = 0; row < 8; row++)
#pragma unroll
        for (int r = 0; r < NROW; r++) acc[row][r] = 0.f;

#pragma unroll
    for (int j = 0; j < 6; j++) {
        float4 xv[NROW];
#pragma unroll
        for (int r = 0; r < NROW; r++)
            xv[r] = *reinterpret_cast<const float4*>(&xs[r][j * 128 + lane * 4]);
#pragma unroll
        for (int row = 0; row < 8; row++) {
            float4 wv = (j == 0) ? wpre[row]
                                 : W4[(8 * w + row) * 192 + j * 32 + lane];
#pragma unroll
            for (int r = 0; r < NROW; r++) {
                acc[row][r] = fmaf(wv.x, xv[r].x, acc[row][r]);
                acc[row][r] = fmaf(wv.y, xv[r].y, acc[row][r]);
                acc[row][r] = fmaf(wv.z, xv[r].z, acc[row][r]);
                acc[row][r] = fmaf(wv.w, xv[r].w, acc[row][r]);
            }
        }
    }
    // butterfly-reduce the 48 accumulators across lanes; lane r stores g
#pragma unroll
    for (int row = 0; row < 8; row++) {
#pragma unroll
        for (int r = 0; r < NROW; r++) {
            float s = acc[row][r];
#pragma unroll
            for (int o = 16; o > 0; o >>= 1)
                s += __shfl_xor_sync(0xffffffffu, s, o);
            if (lane == r) gt[8 * w + row][r] = s;
        }
    }
    __syncthreads();

    // ---- Phase 4: 11 Gram products of the g vectors, warp-parallel ----
    // p even -> (0, p/2), p odd -> (k,k), k=(p+1)/2
    {
        int pidx = w;
        int pa = (pidx & 1) ? (pidx + 1) / 2 : 0;
        int pb = (pidx & 1) ? (pidx + 1) / 2 : pidx / 2;
        float s = gt[lane][pa] * gt[lane][pb] + gt[lane + 32][pa] * gt[lane + 32][pb];
#pragma unroll
        for (int o = 16; o > 0; o >>= 1)
            s += __shfl_xor_sync(0xffffffffu, s, o);
        if (lane == 0) gram[pidx] = s;
        if (w < 3) {
            pidx = 8 + w;
            pa = (pidx & 1) ? (pidx + 1) / 2 : 0;
            pb = (pidx & 1) ? (pidx + 1) / 2 : pidx / 2;
            float s2 = gt[lane][pa] * gt[lane][pb] + gt[lane + 32][pa] * gt[lane + 32][pb];
#pragma unroll
            for (int o = 16; o > 0; o >>= 1)
                s2 += __shfl_xor_sync(0xffffffffu, s2, o);
            if (lane == 0) gram[pidx] = s2;
        }
    }
    __syncthreads();

    // ---- Phase 5: scalar tail on thread 0 ----
    if (t == 0) {
        float nsq[NROW], gsq[NROW], fac[NROW];
#pragma unroll
        for (int r = 0; r < NROW; r++) {
            float s = 0.f;
#pragma unroll
            for (int k = 0; k < 8; k++) s += red[r][k];
            nsq[r] = s;
        }
        gsq[0] = gram[0];
#pragma unroll
        for (int r = 1; r < NROW; r++) gsq[r] = gram[2 * r - 1];
#pragma unroll
        for (int r = 0; r < NROW; r++) {
            float n   = fmaxf(sqrtf(nsq[r]), EPSF);
            float th  = tanhf(n);
            float sc1 = th / n;                       // expmap0 scale
            float gn  = sqrtf(gsq[r]);
            float mn  = fmaxf(sc1 * gn, EPSF);        // ||mx||
            float xn  = fmaxf(th, EPSF);              // ||u0||
            float at  = atanhf(fminf(xn, BNDF));
            fac[r] = tanhf(mn / xn * at) * sc1 / mn;  // y = fac * g
        }
        const float nu2 = fac[0] * fac[0] * gsq[0];
        const float Bc  = 1.f - nu2;
        float dist[5];
#pragma unroll
        for (int bi = 1; bi < NROW; bi++) {
            float nb2 = fac[bi] * fac[bi] * gsq[bi];
            float d   = fac[0] * fac[bi] * gram[2 * bi];
            float A   = 1.f - 2.f * d + nb2;
            float num2 = fmaxf(A * A * nu2 - 2.f * A * Bc * d + Bc * Bc * nb2, 0.f);
            float den  = fmaxf(1.f - 2.f * d + nu2 * nb2, EPSF);
            dist[bi - 1] = 2.f * atanhf(fminf(sqrtf(num2) / den, BNDF));
        }
        // hyperbolic angle (u, v)
        float nv2 = fac[1] * fac[1] * gsq[1];
        float duv = fac[0] * fac[1] * gram[2];
        float euclid = sqrtf(fmaxf(nu2 + nv2 - 2.f * duv, 0.f));
        float nv  = sqrtf(nv2);
        float rad = fmaxf(1.f + nu2 * nv2 - 2.f * duv, EPSF);
        float denA = fmaxf(nv * euclid * sqrtf(rad), EPSF);
        float cosang = (duv * (1.f + nv2) - nv2 * (1.f + nu2)) / denA;
        float angle = acosf(fminf(fmaxf(cosang, -BNDF), BNDF));

        float expneg = expf(-dist[0]);
        float Z1 = expf(-dist[1]) + expf(-dist[2]) + expf(-dist[3]) + expf(-dist[4]);
        float ns_loss = -logf(expneg / (Z1 + expneg));

        g_losses[b] = angle + ns_loss;   // alpha = 0.5
        __threadfence();
        unsigned int c = atomicAdd(&g_counter, 1u);
        s_last = (c == gridDim.x - 1) ? 1 : 0;
    }
    __syncthreads();

    // ---- Phase 6: last block: deterministic mean ----
    if (s_last) {
        float vv = (t < B_) ? g_losses[t] : 0.f;
        if (t < B_) {
#pragma unroll
            for (int o = 16; o > 0; o >>= 1)
                vv += __shfl_xor_sync(0xffffffffu, vv, o);
            if (lane == 0) red[0][w] = vv;
        }
        __syncthreads();
        if (t == 0) {
            out[0] = (red[0][0] + red[0][1]) * (1.f / (float)B_);
            g_counter = 0;   // reset for next graph replay
        }
    }
}

extern "C" void kernel_launch(void* const* d_in, const int* in_sizes, int n_in,
                              void* d_out, int out_size) {
    const float* encoded    = (const float*)d_in[0];
    const float* n_encoded  = (const float*)d_in[1];
    const float* mask1      = (const float*)d_in[2];
    const float* mask2      = (const float*)d_in[3];
    const float* mask_u_neg = (const float*)d_in[4];
    const float* W          = (const float*)d_in[5];
    poincare_kernel<<<B_, 256>>>(encoded, n_encoded, mask1, mask2, mask_u_neg, W,
                                 (float*)d_out);
}

// round 3
// speedup vs baseline: 3.1695x; 1.3857x over previous
#include <cuda_runtime.h>
#include <math.h>
#include <stdint.h>

#define B_   64
#define S_   256
#define H_   768
#define D_   64
#define NEG_ 4
#define NROW 6
#define EPSF 1e-15f
#define BNDF (1.0f - 1e-7f)

__device__ float g_losses[B_];
__device__ unsigned int g_counter = 0;

__device__ __forceinline__ void ffma2(uint64_t& acc, uint64_t a, uint64_t b) {
    asm("fma.rn.f32x2 %0, %1, %2, %0;" : "+l"(acc) : "l"(a), "l"(b));
}
__device__ __forceinline__ uint64_t dup2(float w) {
    uint64_t r;
    asm("mov.b64 %0, {%1, %1};" : "=l"(r) : "r"(__float_as_uint(w)));
    return r;
}

__global__ __launch_bounds__(256)
void poincare_kernel(const float* __restrict__ encoded,
                     const float* __restrict__ n_encoded,
                     const float* __restrict__ mask1,
                     const float* __restrict__ mask2,
                     const float* __restrict__ mask_u_neg,
                     const float* __restrict__ W,
                     float* __restrict__ out) {
    // xs2 (row-pair packed gather buffer) and sacc (accumulator transpose
    // buffer) have disjoint lifetimes separated by a barrier -> union.
    __shared__ union {
        float2 xs2[3][H_];          // 18 KB : (x_{2p}[k], x_{2p+1}[k])
        float  sacc[8][32][25];     // 25.6 KB : per-warp, per-lane, 24 accs (pad 25)
    } u;
    __shared__ float gt[D_][NROW];  // g = W @ x per row
    __shared__ float red[NROW][8];  // warp partials of ||x||^2
    __shared__ float gram[12];
    __shared__ int   sidx[NROW];
    __shared__ int   s_last;

    const int b    = blockIdx.x;
    const int t    = threadIdx.x;
    const int lane = t & 31;
    const int w    = t >> 5;

    // Prefetch W chunk j=0 for this warp's 8 output rows (mask-independent)
    const float4* W4 = reinterpret_cast<const float4*>(W);
    float4 wpre[8];
#pragma unroll
    for (int row = 0; row < 8; row++)
        wpre[row] = W4[(8 * w + row) * 192 + lane];

    // ---- Phase 1: one-hot masks -> token indices ----
    if (mask1[b * S_ + t] > 0.5f) sidx[0] = t;
    if (mask2[b * S_ + t] > 0.5f) sidx[1] = t;
#pragma unroll
    for (int j = 0; j < NEG_; j++)
        if (mask_u_neg[(b * NEG_ + j) * S_ + t] > 0.5f) sidx[2 + j] = t;
    __syncthreads();

    // ---- Phase 2: gather 6 rows, pack row-pairs as float2, norm^2 partials ----
    const float* src[NROW];
    src[0] = encoded + (size_t)(b * S_ + sidx[0]) * H_;
    src[1] = encoded + (size_t)(b * S_ + sidx[1]) * H_;
#pragma unroll
    for (int j = 0; j < NEG_; j++)
        src[2 + j] = n_encoded + (size_t)((b * NEG_ + j) * S_ + sidx[2 + j]) * H_;

    float v[3][NROW];
#pragma unroll
    for (int c = 0; c < 3; c++) {
        const int i = t + 256 * c;
#pragma unroll
        for (int r = 0; r < NROW; r++) v[c][r] = src[r][i];
    }
    float p[NROW];
#pragma unroll
    for (int r = 0; r < NROW; r++) p[r] = 0.f;
#pragma unroll
    for (int c = 0; c < 3; c++) {
        const int i = t + 256 * c;
#pragma unroll
        for (int pr = 0; pr < 3; pr++)
            u.xs2[pr][i] = make_float2(v[c][2 * pr], v[c][2 * pr + 1]);
#pragma unroll
        for (int r = 0; r < NROW; r++) p[r] = fmaf(v[c][r], v[c][r], p[r]);
    }
#pragma unroll
    for (int r = 0; r < NROW; r++) {
#pragma unroll
        for (int o = 16; o > 0; o >>= 1)
            p[r] += __shfl_xor_sync(0xffffffffu, p[r], o);
        if (lane == 0) red[r][w] = p[r];
    }
    __syncthreads();

    // ---- Phase 3: matvec with FFMA2; warp w owns output dims 8w..8w+7 ----
    uint64_t acc2[8][3];
#pragma unroll
    for (int row = 0; row < 8; row++)
#pragma unroll
        for (int pr = 0; pr < 3; pr++) acc2[row][pr] = 0ull;

#pragma unroll
    for (int j = 0; j < 6; j++) {
        // x: 4 consecutive k for each of 3 row-pairs = 2x LDS.128 each
        ulonglong2 xA[3], xB[3];
#pragma unroll
        for (int pr = 0; pr < 3; pr++) {
            const ulonglong2* xp =
                reinterpret_cast<const ulonglong2*>(&u.xs2[pr][j * 128 + lane * 4]);
            xA[pr] = xp[0];
            xB[pr] = xp[1];
        }
#pragma unroll
        for (int row = 0; row < 8; row++) {
            float4 wv = (j == 0) ? wpre[row]
                                 : W4[(8 * w + row) * 192 + j * 32 + lane];
            uint64_t w0 = dup2(wv.x), w1 = dup2(wv.y),
                     w2 = dup2(wv.z), w3 = dup2(wv.w);
#pragma unroll
            for (int pr = 0; pr < 3; pr++) {
                ffma2(acc2[row][pr], w0, xA[pr].x);
                ffma2(acc2[row][pr], w1, xA[pr].y);
                ffma2(acc2[row][pr], w2, xB[pr].x);
                ffma2(acc2[row][pr], w3, xB[pr].y);
            }
        }
    }
    __syncthreads();   // all warps done reading xs2 -> reuse as sacc

    // ---- Phase 4: shared transpose + cross-lane reduce -> gt[d][r] ----
#pragma unroll
    for (int row = 0; row < 8; row++)
#pragma unroll
        for (int pr = 0; pr < 3; pr++) {
            uint64_t a = acc2[row][pr];
            int c = (row * 3 + pr) * 2;
            u.sacc[w][lane][c]     = __uint_as_float((uint32_t)a);
            u.sacc[w][lane][c + 1] = __uint_as_float((uint32_t)(a >> 32));
        }
    __syncthreads();

    for (int o = t; o < D_ * NROW; o += 256) {
        int d = o / NROW, r = o % NROW;
        int wd = d >> 3, row = d & 7;
        int c = (row * 3 + (r >> 1)) * 2 + (r & 1);
        float s = 0.f;
#pragma unroll
        for (int l = 0; l < 32; l++) s += u.sacc[wd][l][c];
        gt[d][r] = s;
    }
    __syncthreads();

    // ---- Phase 5: 11 Gram products (p even -> (0,p/2); p odd -> (k,k)) ----
    {
        int pidx = w;
        int pa = (pidx & 1) ? (pidx + 1) / 2 : 0;
        int pb = (pidx & 1) ? (pidx + 1) / 2 : pidx / 2;
        float s = gt[lane][pa] * gt[lane][pb] + gt[lane + 32][pa] * gt[lane + 32][pb];
#pragma unroll
        for (int o = 16; o > 0; o >>= 1)
            s += __shfl_xor_sync(0xffffffffu, s, o);
        if (lane == 0) gram[pidx] = s;
        if (w < 3) {
            pidx = 8 + w;
            pa = (pidx & 1) ? (pidx + 1) / 2 : 0;
            pb = (pidx & 1) ? (pidx + 1) / 2 : pidx / 2;
            float s2 = gt[lane][pa] * gt[lane][pb] + gt[lane + 32][pa] * gt[lane + 32][pb];
#pragma unroll
            for (int o = 16; o > 0; o >>= 1)
                s2 += __shfl_xor_sync(0xffffffffu, s2, o);
            if (lane == 0) gram[pidx] = s2;
        }
    }
    __syncthreads();

    // ---- Phase 6: lane-parallel scalar tail on warp 0 ----
    if (w == 0) {
        const unsigned FULL = 0xffffffffu;
        // per-lane row data (lanes >= 6 compute on safe dummies)
        int r6 = (lane < NROW) ? lane : 0;
        float nsq_l = red[r6][0] + red[r6][1] + red[r6][2] + red[r6][3] +
                      red[r6][4] + red[r6][5] + red[r6][6] + red[r6][7];
        int gidx = (r6 == 0) ? 0 : 2 * r6 - 1;
        float gsq_l = gram[gidx];

        // mobius_matvec scale factor: y_r = fac_r * g_r
        float n   = fmaxf(sqrtf(nsq_l), EPSF);
        float th  = tanhf(n);
        float sc1 = th / n;
        float gn  = sqrtf(gsq_l);
        float mn  = fmaxf(sc1 * gn, EPSF);
        float xn  = fmaxf(th, EPSF);
        float at  = atanhf(fminf(xn, BNDF));
        float fac = tanhf(mn / xn * at) * sc1 / mn;

        float f0   = __shfl_sync(FULL, fac, 0);
        float gsq0 = __shfl_sync(FULL, gsq_l, 0);
        float nu2  = f0 * f0 * gsq0;
        float Bc   = 1.f - nu2;

        // lanes 1..5: dist(u, row_lane) in closed form over Gram entries
        int gi = (lane >= 1 && lane < NROW) ? 2 * lane : 2;
        float gcr = gram[gi];
        float nb2 = fac * fac * gsq_l;
        float dd  = f0 * fac * gcr;
        float A   = 1.f - 2.f * dd + nb2;
        float num2 = fmaxf(A * A * nu2 - 2.f * A * Bc * dd + Bc * Bc * nb2, 0.f);
        float den  = fmaxf(1.f - 2.f * dd + nu2 * nb2, EPSF);
        float dist = 2.f * atanhf(fminf(sqrtf(num2) / den, BNDF));
        float e    = expf(-dist);

        float expneg = __shfl_sync(FULL, e, 1);
        float Z1 = __shfl_sync(FULL, e, 2) + __shfl_sync(FULL, e, 3) +
                   __shfl_sync(FULL, e, 4) + __shfl_sync(FULL, e, 5);

        if (lane == 0) {
            // hyperbolic angle (u, v)
            float f1   = __shfl_sync(0x1u, fac, 0);  // dummy; real values below
            (void)f1;
            float fv   = 0.f, gsqv = 0.f;
            // recompute v's scalars locally (cheap, avoids extra shfl width issues)
            {
                float nsv = red[1][0] + red[1][1] + red[1][2] + red[1][3] +
                            red[1][4] + red[1][5] + red[1][6] + red[1][7];
                gsqv = gram[1];
                float nn  = fmaxf(sqrtf(nsv), EPSF);
                float t2  = tanhf(nn);
                float s2  = t2 / nn;
                float g2  = sqrtf(gsqv);
                float m2  = fmaxf(s2 * g2, EPSF);
                float x2  = fmaxf(t2, EPSF);
                float a2  = atanhf(fminf(x2, BNDF));
                fv = tanhf(m2 / x2 * a2) * s2 / m2;
            }
            float nv2 = fv * fv * gsqv;
            float duv = f0 * fv * gram[2];
            float euclid = sqrtf(fmaxf(nu2 + nv2 - 2.f * duv, 0.f));
            float nv  = sqrtf(nv2);
            float rad = fmaxf(1.f + nu2 * nv2 - 2.f * duv, EPSF);
            float denA = fmaxf(nv * euclid * sqrtf(rad), EPSF);
            float cosang = (duv * (1.f + nv2) - nv2 * (1.f + nu2)) / denA;
            float angle = acosf(fminf(fmaxf(cosang, -BNDF), BNDF));

            float ns_loss = -logf(expneg / (Z1 + expneg));
            g_losses[b] = angle + ns_loss;   // alpha = 0.5

            __threadfence();
            unsigned int c = atomicAdd(&g_counter, 1u);
            s_last = (c == gridDim.x - 1) ? 1 : 0;
        }
    }
    __syncthreads();

    // ---- Phase 7: last block computes the deterministic mean ----
    if (s_last) {
        __threadfence();
        float vv = (t < B_) ? g_losses[t] : 0.f;
        if (t < B_) {
#pragma unroll
            for (int o = 16; o > 0; o >>= 1)
                vv += __shfl_xor_sync(0xffffffffu, vv, o);
            if (lane == 0) red[0][w] = vv;
        }
        __syncthreads();
        if (t == 0) {
            out[0] = (red[0][0] + red[0][1]) * (1.f / (float)B_);
            g_counter = 0;   // reset for next graph replay
        }
    }
}

extern "C" void kernel_launch(void* const* d_in, const int* in_sizes, int n_in,
                              void* d_out, int out_size) {
    const float* encoded    = (const float*)d_in[0];
    const float* n_encoded  = (const float*)d_in[1];
    const float* mask1      = (const float*)d_in[2];
    const float* mask2      = (const float*)d_in[3];
    const float* mask_u_neg = (const float*)d_in[4];
    const float* W          = (const float*)d_in[5];
    poincare_kernel<<<B_, 256>>>(encoded, n_encoded, mask1, mask2, mask_u_neg, W,
                                 (float*)d_out);
}